// round 15
// baseline (speedup 1.0000x reference)
#include <cuda_runtime.h>
#include <cstdint>

// -------------------- problem constants --------------------
#define TT   4
#define HH   128
#define WW   128
#define CC   256
#define HDN  8
#define KNBR 9
#define FF   32
#define MDIM (TT*HH*WW)   // 65536

// scratch (device globals; no runtime allocation allowed)
__device__ float g_v[(size_t)MDIM * CC];     // v = x @ v_w.T (fp32)
__device__ float g_wv[(size_t)CC * CC];      // v_w tf32-rounded
__device__ float g_wp[(size_t)CC * CC];      // proj_w tf32-rounded

// -------------------- helpers --------------------
__device__ __forceinline__ uint32_t smem_u32(const void* p) {
    uint32_t a;
    asm("{ .reg .u64 t; cvta.to.shared.u64 t, %1; cvt.u32.u64 %0, t; }" : "=r"(a) : "l"(p));
    return a;
}
__device__ __forceinline__ uint32_t f2tf32(float x) {
    uint32_t r; asm("cvt.rna.tf32.f32 %0, %1;" : "=r"(r) : "f"(x)); return r;
}
__device__ __forceinline__ uint32_t rnd_u(uint32_t u) {
    uint32_t r; asm("cvt.rna.tf32.f32 %0, %1;" : "=r"(r) : "f"(__uint_as_float(u))); return r;
}
// Swizzle<3,4,3>
__device__ __forceinline__ uint32_t swz(uint32_t off) {
    return off ^ ((off >> 3) & 0x70);
}
__device__ __forceinline__ void cp_async16(uint32_t dst, const void* src) {
    asm volatile("cp.async.cg.shared.global [%0], [%1], 16;" :: "r"(dst), "l"(src));
}
__device__ __forceinline__ void cp_commit() {
    asm volatile("cp.async.commit_group;" ::: "memory");
}
template <int N>
__device__ __forceinline__ void cp_wait() {
    asm volatile("cp.async.wait_group %0;" :: "n"(N) : "memory");
}
__device__ __forceinline__ void ldmatrix_x4(uint32_t& r0, uint32_t& r1, uint32_t& r2, uint32_t& r3,
                                            uint32_t addr) {
    asm volatile("ldmatrix.sync.aligned.m8n8.x4.shared.b16 {%0,%1,%2,%3}, [%4];"
                 : "=r"(r0), "=r"(r1), "=r"(r2), "=r"(r3) : "r"(addr));
}
__device__ __forceinline__ void mma_tf32(float& c0, float& c1, float& c2, float& c3,
                                         uint32_t a0, uint32_t a1, uint32_t a2, uint32_t a3,
                                         uint32_t b0, uint32_t b1) {
    asm volatile("mma.sync.aligned.m16n8k8.row.col.f32.tf32.tf32.f32 "
                 "{%0,%1,%2,%3}, {%4,%5,%6,%7}, {%8,%9}, {%0,%1,%2,%3};"
                 : "+f"(c0), "+f"(c1), "+f"(c2), "+f"(c3)
                 : "r"(a0), "r"(a1), "r"(a2), "r"(a3), "r"(b0), "r"(b1));
}

// -------------------- tf32 pre-conversion (weights only; tiny) --------------------
__global__ __launch_bounds__(256)
void cvt_tf32_kernel(const float* __restrict__ in, float* __restrict__ out, int n4) {
    int i = blockIdx.x * blockDim.x + threadIdx.x;
    if (i < n4) {
        float4 v = ((const float4*)in)[i];
        uint4 o;
        o.x = f2tf32(v.x); o.y = f2tf32(v.y);
        o.z = f2tf32(v.z); o.w = f2tf32(v.w);
        ((uint4*)out)[i] = o;
    }
}

// -------------------- GEMM1: tf32 mma.sync (R9 config, unchanged) ------------
#define GEMM_BM 128
#define GEMM_BN 128
#define GEMM_BK 32
#define TILE_BYTES (128 * 32 * 4)          // 16 KB
#define BUF_BYTES  (2 * TILE_BYTES)        // 32 KB
#define NSTAGE 3
#define DSMEM_BYTES (NSTAGE * BUF_BYTES)   // 96 KB
#define NKT (CC / GEMM_BK)                 // 8

template <bool CVT_A, bool CVT_B>
__global__ __launch_bounds__(256, 2)
void gemm_tf32_mma_kernel(const float* __restrict__ A,
                          const float* __restrict__ Bw,
                          const float* __restrict__ bias,
                          float* __restrict__ C)
{
    extern __shared__ char sm[];
    const int tid = threadIdx.x;
    const int wid = tid >> 5;
    const int lane = tid & 31;
    const int warp_m = wid >> 2;
    const int warp_n = wid & 3;
    const int bm = blockIdx.y * GEMM_BM;
    const int bn = blockIdx.x * GEMM_BN;

    const uint32_t smbase = smem_u32(sm);

    const int st_c4  = tid & 7;
    const int st_row0 = tid >> 3;
    uint32_t st_off[4];
    #pragma unroll
    for (int i = 0; i < 4; i++)
        st_off[i] = swz((uint32_t)(st_row0 + 32 * i) * 128 + st_c4 * 16);

    const float* Abase = A + (size_t)(bm + st_row0) * CC + st_c4 * 4;
    const float* Bbase = Bw + (size_t)(bn + st_row0) * CC + st_c4 * 4;

    #pragma unroll
    for (int s = 0; s < 2; s++) {
        const uint32_t buf = smbase + s * BUF_BYTES;
        #pragma unroll
        for (int i = 0; i < 4; i++) {
            cp_async16(buf + st_off[i],              Abase + (size_t)i * 32 * CC + s * GEMM_BK);
            cp_async16(buf + TILE_BYTES + st_off[i], Bbase + (size_t)i * 32 * CC + s * GEMM_BK);
        }
        cp_commit();
    }

    float acc[4][4][4];
    #pragma unroll
    for (int mt = 0; mt < 4; mt++)
        #pragma unroll
        for (int nt = 0; nt < 4; nt++)
            #pragma unroll
            for (int r = 0; r < 4; r++)
                acc[mt][nt][r] = 0.0f;

    const int a_row_in = (lane & 7) + ((lane >> 3) & 1) * 8;
    const int a_chunk_hi = (lane >> 4);
    const int b_nt_off = (lane >> 4) * 8;
    const int b_row_in = (lane & 7);
    const int b_chunk_hi = (lane >> 3) & 1;

    #pragma unroll
    for (int kt = 0; kt < NKT; kt++) {
        if (kt + 1 < NKT) cp_wait<1>(); else cp_wait<0>();
        __syncthreads();
        if (kt + 2 < NKT) {
            const uint32_t buf = smbase + ((kt + 2) % NSTAGE) * BUF_BYTES;
            #pragma unroll
            for (int i = 0; i < 4; i++) {
                cp_async16(buf + st_off[i],              Abase + (size_t)i * 32 * CC + (kt + 2) * GEMM_BK);
                cp_async16(buf + TILE_BYTES + st_off[i], Bbase + (size_t)i * 32 * CC + (kt + 2) * GEMM_BK);
            }
            cp_commit();
        }

        const uint32_t abuf = smbase + (kt % NSTAGE) * BUF_BYTES;
        const uint32_t bbuf = abuf + TILE_BYTES;

        #pragma unroll
        for (int kk = 0; kk < 4; kk++) {
            uint32_t af[4][4];
            #pragma unroll
            for (int mt = 0; mt < 4; mt++) {
                const int row = warp_m * 64 + mt * 16 + a_row_in;
                const uint32_t off = swz((uint32_t)row * 128 + (kk * 2 + a_chunk_hi) * 16);
                ldmatrix_x4(af[mt][0], af[mt][1], af[mt][2], af[mt][3], abuf + off);
                if (CVT_A) {
                    af[mt][0] = rnd_u(af[mt][0]); af[mt][1] = rnd_u(af[mt][1]);
                    af[mt][2] = rnd_u(af[mt][2]); af[mt][3] = rnd_u(af[mt][3]);
                }
            }
            uint32_t bf[4][2];
            #pragma unroll
            for (int pair = 0; pair < 2; pair++) {
                const int row = warp_n * 32 + pair * 16 + b_nt_off + b_row_in;
                const uint32_t off = swz((uint32_t)row * 128 + (kk * 2 + b_chunk_hi) * 16);
                uint32_t r0, r1, r2, r3;
                ldmatrix_x4(r0, r1, r2, r3, bbuf + off);
                if (CVT_B) {
                    r0 = rnd_u(r0); r1 = rnd_u(r1); r2 = rnd_u(r2); r3 = rnd_u(r3);
                }
                bf[pair * 2 + 0][0] = r0; bf[pair * 2 + 0][1] = r1;
                bf[pair * 2 + 1][0] = r2; bf[pair * 2 + 1][1] = r3;
            }
            #pragma unroll
            for (int mt = 0; mt < 4; mt++)
                #pragma unroll
                for (int nt = 0; nt < 4; nt++)
                    mma_tf32(acc[mt][nt][0], acc[mt][nt][1], acc[mt][nt][2], acc[mt][nt][3],
                             af[mt][0], af[mt][1], af[mt][2], af[mt][3],
                             bf[nt][0], bf[nt][1]);
        }
    }

    const int er = warp_m * 64 + (lane >> 2);
    const int ec = warp_n * 32 + (lane & 3) * 2;
    #pragma unroll
    for (int mt = 0; mt < 4; mt++) {
        #pragma unroll
        for (int nt = 0; nt < 4; nt++) {
            const int row = bm + er + mt * 16;
            const int col = bn + ec + nt * 8;
            float2 lo = make_float2(acc[mt][nt][0], acc[mt][nt][1]);
            float2 hi = make_float2(acc[mt][nt][2], acc[mt][nt][3]);
            if (bias) {
                const float b0 = bias[col], b1 = bias[col + 1];
                lo.x += b0; lo.y += b1; hi.x += b0; hi.y += b1;
            }
            *(float2*)(C + (size_t)row * CC + col)       = lo;
            *(float2*)(C + (size_t)(row + 8) * CC + col) = hi;
        }
    }
}

// -------------------- FUSED gather + GEMM2 ------------------------------------
// One CTA = one (t,h): rows bm..bm+127 are w=0..127 (W==128==BM).
// k-tile kt == head kt (BK==32==F). A tile for k-tile kt is gathered on the fly:
//   A[w, f] = sum_k attn[kt,t,h,w,k] * v[voff(kt,w,k) + kt*32 + f]   (tf32-rounded)
// B = proj_w (pre-rounded) via 3-stage cp.async. BN=256 (full N), 512 threads.
#define F_BN 256
#define FA_TILE 16384                        // 128 x 32 floats
#define FB_TILE 32768                        // 256 x 32 floats
#define SM_PACK 0                            // 8*128*9 float2 = 73728 B
#define SM_A    73728                        // 2 x FA_TILE = 32768 B
#define SM_B    (73728 + 32768)              // 3 x FB_TILE = 98304 B
#define FUSED_SMEM (SM_B + 3 * FB_TILE)      // 204800 B

__global__ __launch_bounds__(512, 1)
void gemm2_fused_kernel(const float* __restrict__ v,
                        const float* __restrict__ attn,
                        const int*   __restrict__ flows,
                        const float* __restrict__ Bw,
                        const float* __restrict__ bias,
                        float* __restrict__ C)
{
    extern __shared__ char sm[];
    const uint32_t smbase = smem_u32(sm);
    float2* s_pack = (float2*)(sm + SM_PACK);

    const int tid = threadIdx.x;
    const int wid = tid >> 5;          // 0..15
    const int lane = tid & 31;
    const int warp_m = wid >> 3;       // 0..1
    const int warp_n = wid & 7;        // 0..7
    const int th = blockIdx.x;         // t*H + h
    const int t = th >> 7;
    const int h = th & 127;
    const int bm = th * 128;

    // ---- B staging indices (256 rows x 32k; 512 thr -> 4 chunks of 64 rows) ----
    const int st_c4  = tid & 7;
    const int st_row0 = tid >> 3;      // 0..63
    uint32_t b_off[4];
    #pragma unroll
    for (int j = 0; j < 4; j++)
        b_off[j] = swz((uint32_t)(st_row0 + 64 * j) * 128 + st_c4 * 16);
    const float* Bbase = Bw + (size_t)st_row0 * CC + st_c4 * 4;

    // prologue: issue B stages 0,1
    #pragma unroll
    for (int s = 0; s < 2; s++) {
        const uint32_t buf = smbase + SM_B + s * FB_TILE;
        #pragma unroll
        for (int j = 0; j < 4; j++)
            cp_async16(buf + b_off[j], Bbase + (size_t)j * 64 * CC + s * GEMM_BK);
        cp_commit();
    }

    // ---- init: build (attn, voff) table for all 8 heads ----
    for (int j = tid; j < HDN * WW * KNBR; j += 512) {
        const int hd = j / (WW * KNBR);
        const int r  = j - hd * (WW * KNBR);        // w*9 + k
        const int w  = r / KNBR;
        const size_t abase = ((size_t)((hd * TT + t) * HH + h) * WW) * KNBR + r;
        const size_t fbase = abase * 3;
        const float a = __ldg(attn + abase);
        const int dt = __ldg(flows + fbase + 0);
        const int dh = __ldg(flows + fbase + 1);
        const int dw = __ldg(flows + fbase + 2);
        const int tt = min(max(t + dt, 0), TT - 1);
        const int hh = min(max(h + dh, 0), HH - 1);
        const int ww = min(max(w + dw, 0), WW - 1);
        s_pack[j] = make_float2(a, __int_as_float(((tt * HH + hh) * WW + ww) * CC));
    }
    __syncthreads();    // pack ready for gather

    // ---- gather A(0) into A buf 0 ----
    const int gw = tid >> 2;           // w 0..127
    const int gc = tid & 3;            // f4 columns gc and gc+4
    {
        const float2* pk = s_pack + 0 * (WW * KNBR) + gw * KNBR;
        float4 a0 = make_float4(0.f,0.f,0.f,0.f), a1 = a0;
        #pragma unroll
        for (int k = 0; k < KNBR; k++) {
            const float2 p = pk[k];
            const float* vr = v + __float_as_int(p.y) + 0 * FF;
            const float4 x0 = *(const float4*)(vr + gc * 4);
            const float4 x1 = *(const float4*)(vr + (gc + 4) * 4);
            a0.x += p.x * x0.x; a0.y += p.x * x0.y; a0.z += p.x * x0.z; a0.w += p.x * x0.w;
            a1.x += p.x * x1.x; a1.y += p.x * x1.y; a1.z += p.x * x1.z; a1.w += p.x * x1.w;
        }
        uint4 u0, u1;
        u0.x = f2tf32(a0.x); u0.y = f2tf32(a0.y); u0.z = f2tf32(a0.z); u0.w = f2tf32(a0.w);
        u1.x = f2tf32(a1.x); u1.y = f2tf32(a1.y); u1.z = f2tf32(a1.z); u1.w = f2tf32(a1.w);
        char* ab = sm + SM_A;
        *(uint4*)(ab + swz((uint32_t)gw * 128 + gc * 16))       = u0;
        *(uint4*)(ab + swz((uint32_t)gw * 128 + (gc + 4) * 16)) = u1;
    }

    // ---- accumulators ----
    float acc[4][4][4];
    #pragma unroll
    for (int mt = 0; mt < 4; mt++)
        #pragma unroll
        for (int nt = 0; nt < 4; nt++)
            #pragma unroll
            for (int r = 0; r < 4; r++)
                acc[mt][nt][r] = 0.0f;

    const int a_row_in = (lane & 7) + ((lane >> 3) & 1) * 8;
    const int a_chunk_hi = (lane >> 4);
    const int b_nt_off = (lane >> 4) * 8;
    const int b_row_in = (lane & 7);
    const int b_chunk_hi = (lane >> 3) & 1;

    #pragma unroll
    for (int kt = 0; kt < NKT; kt++) {
        if (kt + 1 < NKT) cp_wait<1>(); else cp_wait<0>();
        __syncthreads();   // B(kt) staged; A(kt) STS from prev iter visible

        // issue B(kt+2)
        if (kt + 2 < NKT) {
            const uint32_t buf = smbase + SM_B + ((kt + 2) % 3) * FB_TILE;
            #pragma unroll
            for (int j = 0; j < 4; j++)
                cp_async16(buf + b_off[j], Bbase + (size_t)j * 64 * CC + (kt + 2) * GEMM_BK);
            cp_commit();
        }

        // gather A(kt+1) into the other A buffer (overlaps with mma below)
        if (kt + 1 < NKT) {
            const int hd = kt + 1;
            const float2* pk = s_pack + hd * (WW * KNBR) + gw * KNBR;
            float4 a0 = make_float4(0.f,0.f,0.f,0.f), a1 = a0;
            #pragma unroll
            for (int k = 0; k < KNBR; k++) {
                const float2 p = pk[k];
                const float* vr = v + __float_as_int(p.y) + hd * FF;
                const float4 x0 = *(const float4*)(vr + gc * 4);
                const float4 x1 = *(const float4*)(vr + (gc + 4) * 4);
                a0.x += p.x * x0.x; a0.y += p.x * x0.y; a0.z += p.x * x0.z; a0.w += p.x * x0.w;
                a1.x += p.x * x1.x; a1.y += p.x * x1.y; a1.z += p.x * x1.z; a1.w += p.x * x1.w;
            }
            uint4 u0, u1;
            u0.x = f2tf32(a0.x); u0.y = f2tf32(a0.y); u0.z = f2tf32(a0.z); u0.w = f2tf32(a0.w);
            u1.x = f2tf32(a1.x); u1.y = f2tf32(a1.y); u1.z = f2tf32(a1.z); u1.w = f2tf32(a1.w);
            char* ab = sm + SM_A + ((kt + 1) & 1) * FA_TILE;
            *(uint4*)(ab + swz((uint32_t)gw * 128 + gc * 16))       = u0;
            *(uint4*)(ab + swz((uint32_t)gw * 128 + (gc + 4) * 16)) = u1;
        }

        // mma(kt): A from buf kt&1, B from stage kt%3
        const uint32_t abuf = smbase + SM_A + (kt & 1) * FA_TILE;
        const uint32_t bbuf = smbase + SM_B + (kt % 3) * FB_TILE;

        #pragma unroll
        for (int kk = 0; kk < 4; kk++) {
            uint32_t af[4][4];
            #pragma unroll
            for (int mt = 0; mt < 4; mt++) {
                const int row = warp_m * 64 + mt * 16 + a_row_in;
                const uint32_t off = swz((uint32_t)row * 128 + (kk * 2 + a_chunk_hi) * 16);
                ldmatrix_x4(af[mt][0], af[mt][1], af[mt][2], af[mt][3], abuf + off);
            }
            uint32_t bf[4][2];
            #pragma unroll
            for (int pair = 0; pair < 2; pair++) {
                const int row = warp_n * 32 + pair * 16 + b_nt_off + b_row_in;
                const uint32_t off = swz((uint32_t)row * 128 + (kk * 2 + b_chunk_hi) * 16);
                uint32_t r0, r1, r2, r3;
                ldmatrix_x4(r0, r1, r2, r3, bbuf + off);
                bf[pair * 2 + 0][0] = r0; bf[pair * 2 + 0][1] = r1;
                bf[pair * 2 + 1][0] = r2; bf[pair * 2 + 1][1] = r3;
            }
            #pragma unroll
            for (int mt = 0; mt < 4; mt++)
                #pragma unroll
                for (int nt = 0; nt < 4; nt++)
                    mma_tf32(acc[mt][nt][0], acc[mt][nt][1], acc[mt][nt][2], acc[mt][nt][3],
                             af[mt][0], af[mt][1], af[mt][2], af[mt][3],
                             bf[nt][0], bf[nt][1]);
        }
    }

    // epilogue (+bias)
    const int er = warp_m * 64 + (lane >> 2);
    const int ec = warp_n * 32 + (lane & 3) * 2;
    #pragma unroll
    for (int mt = 0; mt < 4; mt++) {
        #pragma unroll
        for (int nt = 0; nt < 4; nt++) {
            const int row = bm + er + mt * 16;
            const int col = ec + nt * 8;
            float2 lo = make_float2(acc[mt][nt][0], acc[mt][nt][1]);
            float2 hi = make_float2(acc[mt][nt][2], acc[mt][nt][3]);
            const float b0 = bias[col], b1 = bias[col + 1];
            lo.x += b0; lo.y += b1; hi.x += b0; hi.y += b1;
            *(float2*)(C + (size_t)row * CC + col)       = lo;
            *(float2*)(C + (size_t)(row + 8) * CC + col) = hi;
        }
    }
}

// -------------------- launch --------------------
extern "C" void kernel_launch(void* const* d_in, const int* in_sizes, int n_in,
                              void* d_out, int out_size)
{
    const float* x      = (const float*)d_in[0];
    const float* attn   = (const float*)d_in[1];
    const int*   flows  = (const int*)  d_in[2];
    const float* v_w    = (const float*)d_in[3];
    const float* proj_w = (const float*)d_in[4];
    const float* proj_b = (const float*)d_in[5];
    float* out = (float*)d_out;

    float *v_buf, *wv, *wp;
    cudaGetSymbolAddress((void**)&v_buf, g_v);
    cudaGetSymbolAddress((void**)&wv,    g_wv);
    cudaGetSymbolAddress((void**)&wp,    g_wp);

    cudaFuncSetAttribute(gemm_tf32_mma_kernel<true, false>,
                         cudaFuncAttributeMaxDynamicSharedMemorySize, DSMEM_BYTES);
    cudaFuncSetAttribute(gemm2_fused_kernel,
                         cudaFuncAttributeMaxDynamicSharedMemorySize, FUSED_SMEM);

    // 0) pre-round weights (tiny: 2 x 256KB)
    {
        const int n4w = CC * CC / 4;   // 16384
        cvt_tf32_kernel<<<n4w / 256, 256>>>(v_w, wv, n4w);
        cvt_tf32_kernel<<<n4w / 256, 256>>>(proj_w, wp, n4w);
    }

    // 1) v = x @ v_w.T   (A rounded in-register; B pre-rounded)
    {
        dim3 ggrid(CC / GEMM_BN, MDIM / GEMM_BM);   // (2, 512)
        gemm_tf32_mma_kernel<true, false><<<ggrid, 256, DSMEM_BYTES>>>(x, wv, nullptr, v_buf);
    }

    // 2) FUSED gather + projection: out = agg @ proj_w.T + proj_b
    gemm2_fused_kernel<<<TT * HH, 512, FUSED_SMEM>>>(v_buf, attn, flows, wp, proj_b, out);
}

// round 17
// speedup vs baseline: 1.1286x; 1.1286x over previous
#include <cuda_runtime.h>
#include <cstdint>

// -------------------- problem constants --------------------
#define TT   4
#define HH   128
#define WW   128
#define CC   256
#define HDN  8
#define KNBR 9
#define FF   32
#define MDIM (TT*HH*WW)   // 65536

// scratch (device globals; no runtime allocation allowed)
__device__ float g_v[(size_t)MDIM * CC];     // v = x @ v_w.T (fp32)
__device__ float g_agg[(size_t)MDIM * CC];   // aggregated (tf32-rounded bits)
__device__ float g_wv[(size_t)CC * CC];      // v_w tf32-rounded
__device__ float g_wp[(size_t)CC * CC];      // proj_w tf32-rounded
// sync state: [0]=ticket, [1..512]=flag_v per th (target 2), [513..544]=flag_band (target 64)
__device__ int   g_sync[545];

// -------------------- helpers --------------------
__device__ __forceinline__ uint32_t smem_u32(const void* p) {
    uint32_t a;
    asm("{ .reg .u64 t; cvta.to.shared.u64 t, %1; cvt.u32.u64 %0, t; }" : "=r"(a) : "l"(p));
    return a;
}
__device__ __forceinline__ uint32_t f2tf32(float x) {
    uint32_t r; asm("cvt.rna.tf32.f32 %0, %1;" : "=r"(r) : "f"(x)); return r;
}
__device__ __forceinline__ uint32_t rnd_u(uint32_t u) {
    uint32_t r; asm("cvt.rna.tf32.f32 %0, %1;" : "=r"(r) : "f"(__uint_as_float(u))); return r;
}
// Swizzle<3,4,3>
__device__ __forceinline__ uint32_t swz(uint32_t off) {
    return off ^ ((off >> 3) & 0x70);
}
__device__ __forceinline__ void cp_async16(uint32_t dst, const void* src) {
    asm volatile("cp.async.cg.shared.global [%0], [%1], 16;" :: "r"(dst), "l"(src));
}
__device__ __forceinline__ void cp_commit() {
    asm volatile("cp.async.commit_group;" ::: "memory");
}
template <int N>
__device__ __forceinline__ void cp_wait() {
    asm volatile("cp.async.wait_group %0;" :: "n"(N) : "memory");
}
__device__ __forceinline__ void ldmatrix_x4(uint32_t& r0, uint32_t& r1, uint32_t& r2, uint32_t& r3,
                                            uint32_t addr) {
    asm volatile("ldmatrix.sync.aligned.m8n8.x4.shared.b16 {%0,%1,%2,%3}, [%4];"
                 : "=r"(r0), "=r"(r1), "=r"(r2), "=r"(r3) : "r"(addr));
}
__device__ __forceinline__ void mma_tf32(float& c0, float& c1, float& c2, float& c3,
                                         uint32_t a0, uint32_t a1, uint32_t a2, uint32_t a3,
                                         uint32_t b0, uint32_t b1) {
    asm volatile("mma.sync.aligned.m16n8k8.row.col.f32.tf32.tf32.f32 "
                 "{%0,%1,%2,%3}, {%4,%5,%6,%7}, {%8,%9}, {%0,%1,%2,%3};"
                 : "+f"(c0), "+f"(c1), "+f"(c2), "+f"(c3)
                 : "r"(a0), "r"(a1), "r"(a2), "r"(a3), "r"(b0), "r"(b1));
}

// -------------------- tf32 pre-conversion (weights only; tiny) --------------------
__global__ __launch_bounds__(256)
void cvt_tf32_kernel(const float* __restrict__ in, float* __restrict__ out, int n4) {
    int i = blockIdx.x * blockDim.x + threadIdx.x;
    if (i < n4) {
        float4 v = ((const float4*)in)[i];
        uint4 o;
        o.x = f2tf32(v.x); o.y = f2tf32(v.y);
        o.z = f2tf32(v.z); o.w = f2tf32(v.w);
        ((uint4*)out)[i] = o;
    }
}

// -------------------- GEMM tile (device fn; R13 body, 128x128, BK=32) ---------
#define GEMM_BM 128
#define GEMM_BN 128
#define GEMM_BK 32
#define TILE_BYTES (128 * 32 * 4)          // 16 KB
#define BUF_BYTES  (2 * TILE_BYTES)        // 32 KB
#define NSTAGE 3
#define DSMEM_BYTES (NSTAGE * BUF_BYTES)   // 96 KB
#define NKT (CC / GEMM_BK)                 // 8

template <bool CVT_A>
__device__ void gemm_tile(const float* __restrict__ A,
                          const float* __restrict__ Bw,
                          const float* __restrict__ bias,
                          float* __restrict__ C,
                          int bnq, int th, char* sm)
{
    const int tid = threadIdx.x;
    const int wid = tid >> 5;
    const int lane = tid & 31;
    const int warp_m = wid >> 2;
    const int warp_n = wid & 3;
    const int bm = th << 7;
    const int bn = bnq << 7;

    const uint32_t smbase = smem_u32(sm);

    const int st_c4  = tid & 7;
    const int st_row0 = tid >> 3;
    uint32_t st_off[4];
    #pragma unroll
    for (int i = 0; i < 4; i++)
        st_off[i] = swz((uint32_t)(st_row0 + 32 * i) * 128 + st_c4 * 16);

    const float* Abase = A + (size_t)(bm + st_row0) * CC + st_c4 * 4;
    const float* Bbase = Bw + (size_t)(bn + st_row0) * CC + st_c4 * 4;

    #pragma unroll
    for (int s = 0; s < 2; s++) {
        const uint32_t buf = smbase + s * BUF_BYTES;
        #pragma unroll
        for (int i = 0; i < 4; i++) {
            cp_async16(buf + st_off[i],              Abase + (size_t)i * 32 * CC + s * GEMM_BK);
            cp_async16(buf + TILE_BYTES + st_off[i], Bbase + (size_t)i * 32 * CC + s * GEMM_BK);
        }
        cp_commit();
    }

    float acc[4][4][4];
    #pragma unroll
    for (int mt = 0; mt < 4; mt++)
        #pragma unroll
        for (int nt = 0; nt < 4; nt++)
            #pragma unroll
            for (int r = 0; r < 4; r++)
                acc[mt][nt][r] = 0.0f;

    const int a_row_in = (lane & 7) + ((lane >> 3) & 1) * 8;
    const int a_chunk_hi = (lane >> 4);
    const int b_nt_off = (lane >> 4) * 8;
    const int b_row_in = (lane & 7);
    const int b_chunk_hi = (lane >> 3) & 1;

    #pragma unroll
    for (int kt = 0; kt < NKT; kt++) {
        if (kt + 1 < NKT) cp_wait<1>(); else cp_wait<0>();
        __syncthreads();
        if (kt + 2 < NKT) {
            const uint32_t buf = smbase + ((kt + 2) % NSTAGE) * BUF_BYTES;
            #pragma unroll
            for (int i = 0; i < 4; i++) {
                cp_async16(buf + st_off[i],              Abase + (size_t)i * 32 * CC + (kt + 2) * GEMM_BK);
                cp_async16(buf + TILE_BYTES + st_off[i], Bbase + (size_t)i * 32 * CC + (kt + 2) * GEMM_BK);
            }
            cp_commit();
        }

        const uint32_t abuf = smbase + (kt % NSTAGE) * BUF_BYTES;
        const uint32_t bbuf = abuf + TILE_BYTES;

        #pragma unroll
        for (int kk = 0; kk < 4; kk++) {
            uint32_t af[4][4];
            #pragma unroll
            for (int mt = 0; mt < 4; mt++) {
                const int row = warp_m * 64 + mt * 16 + a_row_in;
                const uint32_t off = swz((uint32_t)row * 128 + (kk * 2 + a_chunk_hi) * 16);
                ldmatrix_x4(af[mt][0], af[mt][1], af[mt][2], af[mt][3], abuf + off);
                if (CVT_A) {
                    af[mt][0] = rnd_u(af[mt][0]); af[mt][1] = rnd_u(af[mt][1]);
                    af[mt][2] = rnd_u(af[mt][2]); af[mt][3] = rnd_u(af[mt][3]);
                }
            }
            uint32_t bf[4][2];
            #pragma unroll
            for (int pair = 0; pair < 2; pair++) {
                const int row = warp_n * 32 + pair * 16 + b_nt_off + b_row_in;
                const uint32_t off = swz((uint32_t)row * 128 + (kk * 2 + b_chunk_hi) * 16);
                uint32_t r0, r1, r2, r3;
                ldmatrix_x4(r0, r1, r2, r3, bbuf + off);
                bf[pair * 2 + 0][0] = r0; bf[pair * 2 + 0][1] = r1;
                bf[pair * 2 + 1][0] = r2; bf[pair * 2 + 1][1] = r3;
            }
            #pragma unroll
            for (int mt = 0; mt < 4; mt++)
                #pragma unroll
                for (int nt = 0; nt < 4; nt++)
                    mma_tf32(acc[mt][nt][0], acc[mt][nt][1], acc[mt][nt][2], acc[mt][nt][3],
                             af[mt][0], af[mt][1], af[mt][2], af[mt][3],
                             bf[nt][0], bf[nt][1]);
        }
    }

    const int er = warp_m * 64 + (lane >> 2);
    const int ec = warp_n * 32 + (lane & 3) * 2;
    #pragma unroll
    for (int mt = 0; mt < 4; mt++) {
        #pragma unroll
        for (int nt = 0; nt < 4; nt++) {
            const int row = bm + er + mt * 16;
            const int col = bn + ec + nt * 8;
            float2 lo = make_float2(acc[mt][nt][0], acc[mt][nt][1]);
            float2 hi = make_float2(acc[mt][nt][2], acc[mt][nt][3]);
            if (bias) {
                const float b0 = bias[col], b1 = bias[col + 1];
                lo.x += b0; lo.y += b1; hi.x += b0; hi.y += b1;
            }
            *(float2*)(C + (size_t)row * CC + col)       = lo;
            *(float2*)(C + (size_t)(row + 8) * CC + col) = hi;
        }
    }
}

// -------------------- gather tile (device fn; R13 body) -----------------------
__device__ void gather_tile(const float* __restrict__ v,
                            const float* __restrict__ attn,
                            const int*   __restrict__ flows,
                            float* __restrict__ agg,
                            int hd, int t, int h0, int w0, char* sm)
{
    float* s_attn = (float*)sm;                                 // 9216 B
    int*   s_flows = (int*)(sm + 256 * KNBR * 4);               // 27648 B
    int*   s_voff  = (int*)(sm + 256 * KNBR * 4 + 256 * KNBR * 12); // 9216 B

    const int tid = threadIdx.x;

    const size_t pos00 = ((size_t)((hd * TT + t) * HH + h0)) * WW + w0;
    {
        const float* ab = attn + pos00 * KNBR;
        #pragma unroll
        for (int j = tid; j < 16 * 144; j += 256) {
            const int r = j / 144;
            const int c = j - r * 144;
            s_attn[r * 144 + c] = __ldg(ab + (size_t)r * (WW * KNBR) + c);
        }
        const int* fb = flows + pos00 * (KNBR * 3);
        #pragma unroll
        for (int j = tid; j < 16 * 432; j += 256) {
            const int r = j / 432;
            const int c = j - r * 432;
            s_flows[r * 432 + c] = __ldg(fb + (size_t)r * (WW * KNBR * 3) + c);
        }
    }
    __syncthreads();

    {
        const int pl = tid;
        const int w = w0 + (pl & 15);
        const int h = h0 + (pl >> 4);
        #pragma unroll
        for (int k = 0; k < KNBR; k++) {
            const int dt = s_flows[pl * 27 + k * 3 + 0];
            const int dh = s_flows[pl * 27 + k * 3 + 1];
            const int dw = s_flows[pl * 27 + k * 3 + 2];
            const int tt = min(max(t + dt, 0), TT - 1);
            const int hh = min(max(h + dh, 0), HH - 1);
            const int ww = min(max(w + dw, 0), WW - 1);
            s_voff[pl * KNBR + k] = ((tt * HH + hh) * WW + ww) * CC;
        }
    }
    __syncthreads();

    const int fq  = tid & 7;
    const int pl0 = tid >> 3;
    const int fbyte = hd * FF + fq * 4;
    const float* vb = v + fbyte;
    float* op = agg + ((size_t)((t * HH + (h0 + (pl0 >> 4))) * WW + (w0 + (pl0 & 15)))) * CC + fbyte;
    int sb = pl0 * KNBR;

    #pragma unroll
    for (int i = 0; i < 8; i++) {
        float4 acc = make_float4(0.f, 0.f, 0.f, 0.f);
        #pragma unroll
        for (int k = 0; k < KNBR; k++) {
            const float wk = s_attn[sb + k];
            const int voff = s_voff[sb + k];
            const float4 vv = *(const float4*)(vb + voff);
            acc.x += wk * vv.x; acc.y += wk * vv.y;
            acc.z += wk * vv.z; acc.w += wk * vv.w;
        }
        uint4 o;
        o.x = f2tf32(acc.x); o.y = f2tf32(acc.y);
        o.z = f2tf32(acc.z); o.w = f2tf32(acc.w);
        *(uint4*)op = o;
        sb += 32 * KNBR;
        op += (size_t)2 * WW * CC;
    }
}

// -------------------- persistent ticket pipeline -------------------------------
// Tickets: [0,1024) GEMM1 tiles (bn = tk&1, th = tk>>1)
//          [1024,3072) gather tiles (t-major: t, band, hd, w-tile)
//          [3072,4096) GEMM2 tiles (bn = id&1, th = id>>1)
// flag_v[th] (target 2) gates gather bands; flag_band[t*8+band] (target 64)
// gates GEMM2. Deps always have smaller tickets => deadlock-free.
#define N_TICKETS 4096

__global__ __launch_bounds__(256, 2)
void persistent_kernel(const float* __restrict__ x,
                       const float* __restrict__ attn,
                       const int*   __restrict__ flows,
                       const float* __restrict__ bias,
                       float* __restrict__ out)
{
    extern __shared__ char sm[];
    __shared__ int s_tk;
    const int tid = threadIdx.x;

    for (;;) {
        __syncthreads();    // smem from previous tile fully consumed; s_tk safe to rewrite
        if (tid == 0) s_tk = atomicAdd(&g_sync[0], 1);
        __syncthreads();
        const int tk = s_tk;
        if (tk >= N_TICKETS) return;

        if (tk < 1024) {
            // GEMM1: v = x @ v_w.T (CVT_A in-register; wv pre-rounded)
            gemm_tile<true>(x, g_wv, nullptr, g_v, tk & 1, tk >> 1, sm);
            __threadfence();
            __syncthreads();
            if (tid == 0) atomicAdd(&g_sync[1 + (tk >> 1)], 1);
        } else if (tk < 3072) {
            const int gid = tk - 1024;
            const int t    = gid >> 9;          // 0..3
            const int band = (gid >> 6) & 7;    // 0..7
            const int sub  = gid & 63;
            const int hd   = sub >> 3;          // 0..7
            const int w0   = (sub & 7) << 4;    // 0..112
            if (tid == 0) {
                const int lo = max(0, band * 16 - 3);
                const int hi = min(HH - 1, band * 16 + 18);
                for (int h = lo; h <= hi; ++h) {
                    volatile int* f = &g_sync[1 + (t << 7) + h];
                    while (*f < 2) __nanosleep(64);
                }
            }
            __syncthreads();
            __threadfence();    // acquire: order flag observation before v reads
            gather_tile(g_v, attn, flows, g_agg, hd, t, band << 4, w0, sm);
            __threadfence();
            __syncthreads();
            if (tid == 0) atomicAdd(&g_sync[513 + (t << 3) + band], 1);
        } else {
            const int id2 = tk - 3072;
            const int bn = id2 & 1;
            const int th = id2 >> 1;
            const int t = th >> 7;
            const int band = (th & 127) >> 4;
            if (tid == 0) {
                volatile int* f = &g_sync[513 + (t << 3) + band];
                while (*f < 64) __nanosleep(64);
            }
            __syncthreads();
            __threadfence();    // acquire before agg reads (cp.async from L2)
            gemm_tile<false>(g_agg, g_wp, bias, out, bn, th, sm);
        }
    }
}

// -------------------- launch --------------------
extern "C" void kernel_launch(void* const* d_in, const int* in_sizes, int n_in,
                              void* d_out, int out_size)
{
    const float* x      = (const float*)d_in[0];
    const float* attn   = (const float*)d_in[1];
    const int*   flows  = (const int*)  d_in[2];
    const float* v_w    = (const float*)d_in[3];
    const float* proj_w = (const float*)d_in[4];
    const float* proj_b = (const float*)d_in[5];
    float* out = (float*)d_out;

    float *wv, *wp;
    int* sync_ptr;
    cudaGetSymbolAddress((void**)&wv,       g_wv);
    cudaGetSymbolAddress((void**)&wp,       g_wp);
    cudaGetSymbolAddress((void**)&sync_ptr, g_sync);

    // reset ticket + flags (async memset: graph-capturable, no allocation)
    cudaMemsetAsync(sync_ptr, 0, sizeof(int) * 545, 0);

    // pre-round weights (tiny: 2 x 256KB)
    {
        const int n4w = CC * CC / 4;   // 16384
        cvt_tf32_kernel<<<n4w / 256, 256>>>(v_w, wv, n4w);
        cvt_tf32_kernel<<<n4w / 256, 256>>>(proj_w, wp, n4w);
    }

    cudaFuncSetAttribute(persistent_kernel,
                         cudaFuncAttributeMaxDynamicSharedMemorySize, DSMEM_BYTES);

    // persistent pipeline: 296 CTAs (148 SMs x occ 2) drain 4096 tickets
    persistent_kernel<<<296, 256, DSMEM_BYTES>>>(x, attn, flows, proj_b, out);
}